// round 9
// baseline (speedup 1.0000x reference)
#include <cuda_runtime.h>
#include <cstdint>
#include <cstddef>

#define BSZ   64
#define NI    2048
#define DI    8
#define NO    32
#define DOUT  16

#define BT    8
#define NBT   (BSZ / BT)                   // 8 b-tiles
#define NCH   2
#define NTHREADS 256
#define GRID  296                          // 2/SM; 296 % NBT == 0 -> fixed btile per CTA
#define ITEMS_PER_BT (NI / NCH)            // 1024
#define N_ITEMS (ITEMS_PER_BT * NBT)       // 8192

typedef unsigned long long ull;

__device__ float g_s[BSZ * NO * DOUT];           // zero at entry (squash re-zeros)
__device__ float g_v[BSZ * NO * DOUT];
__device__ float g_blog[(size_t)BSZ * NI * NO];  // 16 MB logits
__device__ unsigned g_ctr;                       // last-CTA ticket

static __device__ __forceinline__ ull pack2(float lo, float hi) {
    ull r; asm("mov.b64 %0,{%1,%2};" : "=l"(r) : "f"(lo), "f"(hi)); return r;
}
static __device__ __forceinline__ float2 unpk(ull v) {
    float2 r; asm("mov.b64 {%0,%1},%2;" : "=f"(r.x), "=f"(r.y) : "l"(v)); return r;
}
static __device__ __forceinline__ ull fma2(ull a, ull b, ull c) {
    ull d; asm("fma.rn.f32x2 %0,%1,%2,%3;" : "=l"(d) : "l"(a), "l"(b), "l"(c)); return d;
}
static __device__ __forceinline__ ull mul2(ull a, ull b) {
    ull d; asm("mul.rn.f32x2 %0,%1,%2;" : "=l"(d) : "l"(a), "l"(b)); return d;
}
static __device__ __forceinline__ unsigned s2u(const void* p) {
    return (unsigned)__cvta_generic_to_shared(p);
}
#define CPA16(dst, src) \
    asm volatile("cp.async.cg.shared.global [%0], [%1], 16;" :: "r"(dst), "l"(src) : "memory")
#define CPA_COMMIT() asm volatile("cp.async.commit_group;" ::: "memory")
#define CPA_WAIT0()  asm volatile("cp.async.wait_group 0;"  ::: "memory")

static __device__ __forceinline__ void do_squash(float* __restrict__ dst)
{
#pragma unroll
    for (int rr = 0; rr < 8; rr++) {
        int row = threadIdx.x * 8 + rr;            // 2048 rows of 16
        const float* p = g_s + row * 16;
        float4 a = *(const float4*)(p + 0);
        float4 b = *(const float4*)(p + 4);
        float4 c = *(const float4*)(p + 8);
        float4 d = *(const float4*)(p + 12);
        float sq = a.x*a.x + a.y*a.y + a.z*a.z + a.w*a.w
                 + b.x*b.x + b.y*b.y + b.z*b.z + b.w*b.w
                 + c.x*c.x + c.y*c.y + c.z*c.z + c.w*c.w
                 + d.x*d.x + d.y*d.y + d.z*d.z + d.w*d.w;
        float f = sqrtf(sq) / (1.0f + sq);
        float* q = dst + row * 16;
        *(float4*)(q + 0)  = make_float4(a.x*f, a.y*f, a.z*f, a.w*f);
        *(float4*)(q + 4)  = make_float4(b.x*f, b.y*f, b.z*f, b.w*f);
        *(float4*)(q + 8)  = make_float4(c.x*f, c.y*f, c.z*f, c.w*f);
        *(float4*)(q + 12) = make_float4(d.x*f, d.y*f, d.z*f, d.w*f);
        float4 z = make_float4(0.f, 0.f, 0.f, 0.f);
        float* zp = g_s + row * 16;
        *(float4*)(zp + 0) = z; *(float4*)(zp + 4) = z;
        *(float4*)(zp + 8) = z; *(float4*)(zp + 12) = z;
    }
}

// W SMEM: verbatim 16B gmem units (cp.async), swizzled placement
//   gmem unit g = o*32 + r,  r = 8*dg + 2*dd + ih  (d = dg*4+dd, ih = i-half)
//   smem unit s = o*32 + dd*8 + dg*2 + (ih ^ (o&1))
// Compute-phase bank-col = dg*2 + (ih ^ (o&1)) -> 8 distinct per 8-lane phase.
template <int PASS>
__global__ void __launch_bounds__(NTHREADS, 2)
caps_pass(const float* __restrict__ X, const float* __restrict__ W,
          float* __restrict__ vout)
{
    extern __shared__ char sm[];
    char*   wbuf0 = sm;                               // 32768 B
    char*   wbuf1 = sm + 32768;                       // 32768 B
    float2* xd0   = (float2*)(sm + 65536);            // 1024 B
    float2* xd1   = (float2*)(sm + 65536 + 1024);     // 1024 B
    float*  v_s   = (float*)(sm + 65536 + 2048);      // 16384 B
    float*  red   = (float*)(sm + 65536 + 2048 + 16384); // 128 B
    __shared__ int s_last;

    const int tid = threadIdx.x;
    const int wg  = tid >> 7;            // 0..1
    const int wt  = tid & 127;
    const int o   = wt >> 2;
    const int dg  = wt & 3;
    const int wiw = (wt >> 5) & 3;
    const unsigned par = (unsigned)(o & 1);

    // W-staging coords: 128 threads per n; each copies 8 contiguous gmem units
    const int snn = tid >> 7;
    const int t7  = tid & 127;
    const int so  = t7 >> 2;
    const int sq  = t7 & 3;

    const int btile = blockIdx.x & (NBT - 1);   // fixed per CTA (GRID % NBT == 0)

    const ull Z = pack2(0.f, 0.f);
    ull s0[4], s1[4];
#pragma unroll
    for (int b = 0; b < 4; b++) { s0[b] = Z; s1[b] = Z; }

    // ---- v tile (fixed b-tile): load once ----
    if (PASS > 0) {
#pragma unroll
        for (int k = 0; k < 4; k++) {       // 8 batches * 512 = 4096 floats
            int f = k * 1024 + tid * 4;
            *(float4*)(v_s + f) = *(const float4*)(g_v + (size_t)btile * BT * 512 + f);
        }
    }

    // ---- prologue: async W for first item; x in a register ----
    float xv = 0.f;
    {
        int it0 = blockIdx.x;
        if (it0 < N_ITEMS) {
            const int n0 = (it0 >> 3) * NCH;
            const float* gsrc = W + (size_t)(n0 + snn) * 4096 + so * 128 + sq * 32;
            char* dbase = wbuf0 + snn * 16384 + so * 512;
#pragma unroll
            for (int k = 0; k < 8; k++) {
                int r = sq * 8 + k;
                int rdg = r >> 3, rdd = (r >> 1) & 3, rih = r & 1;
                unsigned s = (unsigned)(rdd * 8 + rdg * 2 + (rih ^ (so & 1)));
                CPA16(s2u(dbase + s * 16), gsrc + k * 4);
            }
            CPA_COMMIT();
            if (tid < 128)
                xv = X[(size_t)(btile * BT + (tid >> 4)) * (NI * DI) + n0 * DI + (tid & 15)];
        }
    }

    int p = 0;
    for (int it = blockIdx.x; it < N_ITEMS; it += GRID) {
        char*   w_s = p ? wbuf1 : wbuf0;
        float2* x_d = p ? xd1  : xd0;

        CPA_WAIT0();                         // this item's W landed (thread-local)
        if (tid < 128) x_d[tid] = make_float2(xv, xv);   // this item's x (dup)
        __syncthreads();                     // publish W + x; prior compute done

        // ---- launch next item's staging into the other buffer ----
        const int itn = it + GRID;
        if (itn < N_ITEMS) {
            const int n0n = (itn >> 3) * NCH;
            const float* gsrc = W + (size_t)(n0n + snn) * 4096 + so * 128 + sq * 32;
            char* dbase = (p ? wbuf0 : wbuf1) + snn * 16384 + so * 512;
#pragma unroll
            for (int k = 0; k < 8; k++) {
                int r = sq * 8 + k;
                int rdg = r >> 3, rdd = (r >> 1) & 3, rih = r & 1;
                unsigned s = (unsigned)(rdd * 8 + rdg * 2 + (rih ^ (so & 1)));
                CPA16(s2u(dbase + s * 16), gsrc + k * 4);
            }
            CPA_COMMIT();
            if (tid < 128)
                xv = X[(size_t)(btile * BT + (tid >> 4)) * (NI * DI) + n0n * DI + (tid & 15)];
        }

        const int n0 = (it >> 3) * NCH;
#pragma unroll 1
        for (int nn = 0; nn < NCH; nn++) {
            const int n = n0 + nn;

            // 8 conflict-free LDS.128 -> pack into fma2 operand pairs
            ull w0[8], w1[8];
            {
                const char* wb = w_s + nn * 16384 + o * 512;
#pragma unroll
                for (int ih = 0; ih < 2; ih++) {
                    float4 A = *(const float4*)(wb + ((unsigned)(0 * 8 + dg * 2 + (ih ^ par))) * 16);
                    float4 B = *(const float4*)(wb + ((unsigned)(1 * 8 + dg * 2 + (ih ^ par))) * 16);
                    w0[ih * 4 + 0] = pack2(A.x, B.x); w0[ih * 4 + 1] = pack2(A.y, B.y);
                    w0[ih * 4 + 2] = pack2(A.z, B.z); w0[ih * 4 + 3] = pack2(A.w, B.w);
                }
#pragma unroll
                for (int ih = 0; ih < 2; ih++) {
                    float4 A = *(const float4*)(wb + ((unsigned)(2 * 8 + dg * 2 + (ih ^ par))) * 16);
                    float4 B = *(const float4*)(wb + ((unsigned)(3 * 8 + dg * 2 + (ih ^ par))) * 16);
                    w1[ih * 4 + 0] = pack2(A.x, B.x); w1[ih * 4 + 1] = pack2(A.y, B.y);
                    w1[ih * 4 + 2] = pack2(A.z, B.z); w1[ih * 4 + 3] = pack2(A.w, B.w);
                }
            }

            if (PASS == 0) {
                const ull C = pack2(0.03125f, 0.03125f);
#pragma unroll
                for (int bi = 0; bi < 4; bi++) {
                    const ulonglong2* xq = (const ulonglong2*)(x_d + (wg * 4 + bi) * 16 + nn * 8);
                    ulonglong2 qa = xq[0];
                    ull h0 = fma2(w0[0], qa.x, mul2(w0[1], qa.y));
                    ull h1 = fma2(w1[0], qa.x, mul2(w1[1], qa.y));
                    ulonglong2 qb = xq[1];
                    h0 = fma2(w0[2], qb.x, h0); h1 = fma2(w1[2], qb.x, h1);
                    h0 = fma2(w0[3], qb.y, h0); h1 = fma2(w1[3], qb.y, h1);
                    ulonglong2 qc = xq[2];
                    h0 = fma2(w0[4], qc.x, h0); h1 = fma2(w1[4], qc.x, h1);
                    h0 = fma2(w0[5], qc.y, h0); h1 = fma2(w1[5], qc.y, h1);
                    ulonglong2 qd = xq[3];
                    h0 = fma2(w0[6], qd.x, h0); h1 = fma2(w1[6], qd.x, h1);
                    h0 = fma2(w0[7], qd.y, h0); h1 = fma2(w1[7], qd.y, h1);
                    s0[bi] = fma2(C, h0, s0[bi]);
                    s1[bi] = fma2(C, h1, s1[bi]);
                }
            } else {
                ull t0[4], t1[4];
#pragma unroll 2
                for (int q = 0; q < 4; q++) {
                    const int bloc = wg * 4 + q;
                    const ulonglong2* xq = (const ulonglong2*)(x_d + bloc * 16 + nn * 8);
                    ulonglong2 qa = xq[0];
                    ull h0 = fma2(w0[0], qa.x, mul2(w0[1], qa.y));
                    ull h1 = fma2(w1[0], qa.x, mul2(w1[1], qa.y));
                    ulonglong2 qb = xq[1];
                    h0 = fma2(w0[2], qb.x, h0); h1 = fma2(w1[2], qb.x, h1);
                    h0 = fma2(w0[3], qb.y, h0); h1 = fma2(w1[3], qb.y, h1);
                    ulonglong2 qc = xq[2];
                    h0 = fma2(w0[4], qc.x, h0); h1 = fma2(w1[4], qc.x, h1);
                    h0 = fma2(w0[5], qc.y, h0); h1 = fma2(w1[5], qc.y, h1);
                    ulonglong2 qd = xq[3];
                    h0 = fma2(w0[6], qd.x, h0); h1 = fma2(w1[6], qd.x, h1);
                    h0 = fma2(w0[7], qd.y, h0); h1 = fma2(w1[7], qd.y, h1);

                    const ulonglong2 vv = *(const ulonglong2*)(v_s + bloc * 512 + o * DOUT + dg * 4);
                    float2 tf = unpk(fma2(h1, vv.y, mul2(h0, vv.x)));
                    float t = tf.x + tf.y;
                    if (PASS == 2 && dg == 0)
                        t += g_blog[(size_t)(btile * BT + bloc) * (NI * NO) + (size_t)n * NO + o];
                    t += __shfl_xor_sync(0xffffffffu, t, 1);
                    t += __shfl_xor_sync(0xffffffffu, t, 2);   // full 16-d dot (+blog)
                    if (PASS == 1 && dg == 0)
                        g_blog[(size_t)(btile * BT + bloc) * (NI * NO) + (size_t)n * NO + o] = t;

                    float e = __expf(t);
                    ull ee = pack2(e, e);
                    t0[q] = mul2(ee, h0);
                    t1[q] = mul2(ee, h1);
                    float ws = e;
                    ws += __shfl_xor_sync(0xffffffffu, ws, 4);
                    ws += __shfl_xor_sync(0xffffffffu, ws, 8);
                    ws += __shfl_xor_sync(0xffffffffu, ws, 16);  // 8 o's in warp
                    if ((tid & 31) == 0) red[wg * 16 + q * 4 + wiw] = ws;
                }
                asm volatile("bar.sync %0, 128;" :: "r"(wg + 1) : "memory");
#pragma unroll
                for (int q = 0; q < 4; q++) {
                    float4 r4 = *(const float4*)(red + wg * 16 + q * 4);
                    float rc = __fdividef(1.f, (r4.x + r4.y) + (r4.z + r4.w));
                    ull cc = pack2(rc, rc);
                    s0[q] = fma2(cc, t0[q], s0[q]);
                    s1[q] = fma2(cc, t1[q], s1[q]);
                }
            }
        }
        p ^= 1;
    }

    // final flush (one b-tile per CTA)
#pragma unroll
    for (int bi = 0; bi < 4; bi++) {
        float* gp = g_s + (size_t)(btile * BT + wg * 4 + bi) * 512 + o * 16 + dg * 4;
        float2 a = unpk(s0[bi]); float2 b = unpk(s1[bi]);
        atomicAdd(gp + 0, a.x); atomicAdd(gp + 1, a.y);
        atomicAdd(gp + 2, b.x); atomicAdd(gp + 3, b.y);
    }

    // last-CTA squash
    __threadfence();
    if (tid == 0) {
        unsigned t = atomicAdd(&g_ctr, 1u);
        s_last = (t == GRID - 1) ? 1 : 0;
    }
    __syncthreads();
    if (s_last) {
        __threadfence();
        do_squash(vout);
        if (tid == 0) g_ctr = 0;   // deterministic across graph replays
    }
}

extern "C" void kernel_launch(void* const* d_in, const int* in_sizes, int n_in,
                              void* d_out, int out_size)
{
    const float* X = (const float*)d_in[0];
    const float* W = (const float*)d_in[1];
    if (in_sizes[0] != BSZ * NI * DI) { X = (const float*)d_in[1]; W = (const float*)d_in[0]; }

    float* vdev = nullptr;
    cudaGetSymbolAddress((void**)&vdev, g_v);

    const int smem = 65536 + 2048 + 16384 + 128;   // 84096 B (x2 CTAs = 168 KB/SM)
    cudaFuncSetAttribute(caps_pass<0>, cudaFuncAttributeMaxDynamicSharedMemorySize, smem);
    cudaFuncSetAttribute(caps_pass<1>, cudaFuncAttributeMaxDynamicSharedMemorySize, smem);
    cudaFuncSetAttribute(caps_pass<2>, cudaFuncAttributeMaxDynamicSharedMemorySize, smem);

    caps_pass<0><<<GRID, NTHREADS, smem>>>(X, W, vdev);
    caps_pass<1><<<GRID, NTHREADS, smem>>>(X, W, vdev);
    caps_pass<2><<<GRID, NTHREADS, smem>>>(X, W, (float*)d_out);
}